// round 9
// baseline (speedup 1.0000x reference)
#include <cuda_runtime.h>

// QORNN: B=256, T=1024, I=64, H=256, O=16
// Exact integer formulation (bit-exact vs the JAX fp32 reference):
//   xq  = clip(rint(x*128), -128, 127)              (int8)
//   wiq = clip(rint(Wi*8),  -8, 7)
//   wrq = clip(rint(Wr*8),  -8, 7)
//   woq = clip(rint(Wo*8),  -8, 7)
//   z_int = sum_i xq*wiq + sum_k hq*wrq             (|.| <= 327680 < 2^24)
//   m  = max(fma(|z|, 1/8, 128*b[j]), 0)            (== 128*ref-m; az*0.125
//                                                    exact, single rounding)
//   hq = sign(z)*clip(rint(m), ..)                  in [-128,127]
//   out[b,o] = (sum_j hq*woq) / 1024
//
// Layout: one CTA (128 threads) per batch row; thread j owns output columns
// j and j+128, sharing every h/x smem read between the two dot products
// (halves smem traffic vs 1 col/thread). x is loaded 8 steps ahead into a
// smem ring (handled by even lanes so all 4 warps carry equal extra work),
// and u(t+1) = xq(t+1).Wi is computed during step t's epilogue window.

#define BB 256
#define TT 1024
#define II 64
#define HH 256
#define OO 16

// Packed quantized weights (allocation-free rule: __device__ globals)
__device__ int d_wr4[64 * HH];      // [q][j]: packed wrq[j][4q..4q+3]
__device__ int d_wi4[16 * HH];      // [q][j]: packed wiq[j][4q..4q+3]
__device__ int d_wo4[OO * 64];      // [o][q]: packed woq[o][4q..4q+3]

__device__ __forceinline__ int clampi(int v, int lo, int hi) {
    return v < lo ? lo : (v > hi ? hi : v);
}

// Quantize 4 floats (round-half-even, clip) and pack into one dp4a word.
__device__ __forceinline__ int qpack4(float4 v, float s, int lo, int hi) {
    int a = clampi(__float2int_rn(v.x * s), lo, hi);
    int b = clampi(__float2int_rn(v.y * s), lo, hi);
    int c = clampi(__float2int_rn(v.z * s), lo, hi);
    int d = clampi(__float2int_rn(v.w * s), lo, hi);
    return (a & 255) | ((b & 255) << 8) | ((c & 255) << 16) | ((d & 255) << 24);
}

// ---------------------------------------------------------------------------
// Kernel 1: quantize + pack all weights. 256 CTAs x 64 threads.
// ---------------------------------------------------------------------------
__global__ void __launch_bounds__(64) pack_weights_kernel(
        const float* __restrict__ Wi,
        const float* __restrict__ Wr,
        const float* __restrict__ Wo) {
    int j = blockIdx.x;   // 0..255
    int q = threadIdx.x;  // 0..63

    const float4* wr = (const float4*)(Wr + j * HH);
    d_wr4[q * HH + j] = qpack4(wr[q], 8.0f, -8, 7);

    if (q < 16) {
        const float4* wi = (const float4*)(Wi + j * II);
        d_wi4[q * HH + j] = qpack4(wi[q], 8.0f, -8, 7);
    }
    if (j < OO) {
        const float4* wo = (const float4*)(Wo + j * HH);
        d_wo4[j * 64 + q] = qpack4(wo[q], 8.0f, -8, 7);
    }
}

// ---------------------------------------------------------------------------
// Kernel 2: fused projection + recurrence + output head.
// ---------------------------------------------------------------------------
__global__ void __launch_bounds__(128, 2)
rnn_kernel(const float* __restrict__ X, const float* __restrict__ bvec,
           float* __restrict__ out) {
    __shared__ int4 hs[2][16];    // two 256-byte h buffers
    __shared__ int4 xring[8][4];  // 8-step ring of packed xq (64 bytes/slot)
    __shared__ int  stagger_sink;

    int b = blockIdx.x;
    int j = threadIdx.x;          // 0..127; owns columns j and j+128
    int j2 = j + 128;

    int w0[64], w1[64];
#pragma unroll
    for (int q = 0; q < 64; q++) {
        w0[q] = d_wr4[q * HH + j];
        w1[q] = d_wr4[q * HH + j2];
    }
    int wi0[16], wi1[16];
#pragma unroll
    for (int q = 0; q < 16; q++) {
        wi0[q] = d_wi4[q * HH + j];
        wi1[q] = d_wi4[q * HH + j2];
    }

    float bj0 = bvec[j]  * 128.0f;   // exact power-of-2 scaling
    float bj1 = bvec[j2] * 128.0f;

    if (j < 32) ((int4*)hs)[j] = make_int4(0, 0, 0, 0);  // h0 = 0, both bufs

    // x pipeline ownership: even lanes (16 per warp, all 4 warps) each own
    // one x column xc = j/2. Ring slots 0..6 <- xq(0..6); x(7) in rcur.
    bool xown = (j & 1) == 0;
    int  xc   = j >> 1;
    const float* xp = X + (size_t)b * TT * II + xc;
    float rcur = 0.0f;
    if (xown) {
        signed char* ring = (signed char*)xring;
#pragma unroll
        for (int p = 0; p < 7; p++) {
            int v = clampi(__float2int_rn(xp[p * II] * 128.0f), -128, 127);
            ring[p * 64 + xc] = (signed char)v;
        }
        rcur = xp[7 * II];
    }

    if (b >= 148) {
        // ~400-cycle dependent-IMAD delay: anti-phase vs co-resident CTA.
        int x = j | 1;
#pragma unroll 1
        for (int i = 0; i < 96; i++) x = x * x + j;
        if (x == 13) stagger_sink = x;  // keep chain alive; never read
    }
    __syncthreads();

    // u(0) for both columns from ring slot 0.
    int uacc0, uacc1;
    {
        const int4* xw = xring[0];
        int c0 = 0, c1 = 0, d0 = 0, d1 = 0;
#pragma unroll
        for (int g = 0; g < 4; g++) {
            int4 xv = xw[g];
            c0 = __dp4a(xv.x, wi0[4 * g + 0], c0);
            c1 = __dp4a(xv.y, wi0[4 * g + 1], c1);
            c0 = __dp4a(xv.z, wi0[4 * g + 2], c0);
            c1 = __dp4a(xv.w, wi0[4 * g + 3], c1);
            d0 = __dp4a(xv.x, wi1[4 * g + 0], d0);
            d1 = __dp4a(xv.y, wi1[4 * g + 1], d1);
            d0 = __dp4a(xv.z, wi1[4 * g + 2], d0);
            d1 = __dp4a(xv.w, wi1[4 * g + 3], d1);
        }
        uacc0 = c0 + c1;
        uacc1 = d0 + d1;
    }

#pragma unroll 1
    for (int tb = 0; tb < TT; tb += 8) {
#pragma unroll
        for (int uu = 0; uu < 8; uu++) {
            int t = tb + uu;

            // ---- h-dots for both columns: 128 dp4a, h loads shared ----
            const int4* hp = hs[uu & 1];
            int a0 = 0, a1 = 0, a2 = 0, a3 = 0;  // column j
            int e0 = 0, e1 = 0, e2 = 0, e3 = 0;  // column j+128
#pragma unroll
            for (int g = 0; g < 16; g++) {
                int4 hv = hp[g];
                a0 = __dp4a(hv.x, w0[4 * g + 0], a0);
                a1 = __dp4a(hv.y, w0[4 * g + 1], a1);
                a2 = __dp4a(hv.z, w0[4 * g + 2], a2);
                a3 = __dp4a(hv.w, w0[4 * g + 3], a3);
                e0 = __dp4a(hv.x, w1[4 * g + 0], e0);
                e1 = __dp4a(hv.y, w1[4 * g + 1], e1);
                e2 = __dp4a(hv.z, w1[4 * g + 2], e2);
                e3 = __dp4a(hv.w, w1[4 * g + 3], e3);
            }
            int z0 = uacc0 + ((a0 + a1) + (a2 + a3));
            int z1 = uacc1 + ((e0 + e1) + (e2 + e3));

            // ---- x pipeline (h-independent; fills epilogue window) ----
            if (xown) {
                int tn = t + 8;
                if (tn > TT - 1) tn = TT - 1;
                float rnext = xp[tn * II];
                int v = clampi(__float2int_rn(rcur * 128.0f), -128, 127);
                ((signed char*)xring[(uu + 7) & 7])[xc] = (signed char)v;
                rcur = rnext;
            }
            // u(t+1) for both columns from ring slot (t+1)&7 (6 barriers old).
            {
                const int4* xw = xring[(uu + 1) & 7];
                int c0 = 0, c1 = 0, d0 = 0, d1 = 0;
#pragma unroll
                for (int g = 0; g < 4; g++) {
                    int4 xv = xw[g];
                    c0 = __dp4a(xv.x, wi0[4 * g + 0], c0);
                    c1 = __dp4a(xv.y, wi0[4 * g + 1], c1);
                    c0 = __dp4a(xv.z, wi0[4 * g + 2], c0);
                    c1 = __dp4a(xv.w, wi0[4 * g + 3], c1);
                    d0 = __dp4a(xv.x, wi1[4 * g + 0], d0);
                    d1 = __dp4a(xv.y, wi1[4 * g + 1], d1);
                    d0 = __dp4a(xv.z, wi1[4 * g + 2], d0);
                    d1 = __dp4a(xv.w, wi1[4 * g + 3], d1);
                }
                uacc0 = c0 + c1;
                uacc1 = d0 + d1;
            }

            // ---- modReLU + 8-bit requantization, both columns ----
            int az0 = z0 < 0 ? -z0 : z0;
            int az1 = z1 < 0 ? -z1 : z1;
            float m0 = fminf(fmaxf(fmaf((float)az0, 0.125f, bj0), 0.0f), 128.0f);
            float m1 = fminf(fmaxf(fmaf((float)az1, 0.125f, bj1), 0.0f), 128.0f);
            int r0 = __float2int_rn(m0);
            int r1 = __float2int_rn(m1);
            int rp0 = r0 < 127 ? r0 : 127;
            int rp1 = r1 < 127 ? r1 : 127;
            int hq0 = (z0 > 0) ? rp0 : (z0 < 0 ? -r0 : 0);
            int hq1 = (z1 > 0) ? rp1 : (z1 < 0 ? -r1 : 0);

            signed char* hn = (signed char*)hs[(uu + 1) & 1];
            hn[j]  = (signed char)hq0;
            hn[j2] = (signed char)hq1;
            __syncthreads();
        }
    }

    // Output head: out[b,o] = (h_last . woq_row(o)) / 1024. Final h in hs[0]
    // (T even: last step wrote buffer (uu+1)&1 == 0).
    if (j < OO) {
        const int* hw = (const int*)hs[0];
        int acc = 0;
#pragma unroll
        for (int g = 0; g < 64; g++) acc = __dp4a(hw[g], d_wo4[j * 64 + g], acc);
        out[b * OO + j] = (float)acc * (1.0f / 1024.0f);
    }
}

// ---------------------------------------------------------------------------
extern "C" void kernel_launch(void* const* d_in, const int* in_sizes, int n_in,
                              void* d_out, int out_size) {
    const float* X  = (const float*)d_in[0];  // inputs [256,1024,64]
    const float* Wi = (const float*)d_in[1];  // [256,64]
    const float* Wr = (const float*)d_in[2];  // [256,256]
    const float* Wo = (const float*)d_in[3];  // [16,256]
    const float* bv = (const float*)d_in[4];  // [256]

    pack_weights_kernel<<<256, 64>>>(Wi, Wr, Wo);
    rnn_kernel<<<BB, 128>>>(X, bv, (float*)d_out);
}